// round 1
// baseline (speedup 1.0000x reference)
#include <cuda_runtime.h>

#define BB 128
#define NN 16384
#define HH 512
#define WW 512
#define NPIX ((size_t)BB * HH * WW)   // 33,554,432 pixels

// Scratch image. __device__ globals are zero-initialized at module load;
// the loss kernel resets it to zero after reading, preserving the
// "zero at entry" invariant across graph replays.
__device__ float g_img[BB * HH * WW];
__device__ double g_sum;

__global__ void init_kernel() { g_sum = 0.0; }

__global__ void splat_kernel(const float* __restrict__ pts) {
    int idx = blockIdx.x * blockDim.x + threadIdx.x;
    if (idx >= BB * NN) return;
    // pts layout [B, N, 3]
    float x     = pts[idx * 3 + 0];
    float y     = pts[idx * 3 + 1];
    float inten = pts[idx * 3 + 2];

    x = fminf(fmaxf(x, 0.0f), (float)(WW - 1));
    y = fminf(fmaxf(y, 0.0f), (float)(HH - 1));
    float x0f = floorf(x);
    float y0f = floorf(y);
    float fx = x - x0f;
    float fy = y - y0f;
    int x0 = (int)x0f;
    int y0 = (int)y0f;
    int x1 = min(x0 + 1, WW - 1);
    int y1 = min(y0 + 1, HH - 1);

    int b = idx / NN;
    float* img = g_img + (size_t)b * HH * WW;

    float w00 = inten * (1.0f - fx) * (1.0f - fy);
    float w01 = inten * fx * (1.0f - fy);
    float w10 = inten * (1.0f - fx) * fy;
    float w11 = inten * fx * fy;

    atomicAdd(&img[y0 * WW + x0], w00);   // return unused -> REDG
    atomicAdd(&img[y0 * WW + x1], w01);
    atomicAdd(&img[y1 * WW + x0], w10);
    atomicAdd(&img[y1 * WW + x1], w11);
}

// Read img + target, accumulate squared diff, reset img to 0 (fused).
__global__ void loss_kernel(const float4* __restrict__ tgt) {
    float4* img4 = reinterpret_cast<float4*>(g_img);
    const size_t n4 = NPIX / 4;
    size_t stride = (size_t)gridDim.x * blockDim.x;
    float acc = 0.0f;

    const float4 zero4 = make_float4(0.f, 0.f, 0.f, 0.f);
    for (size_t i = (size_t)blockIdx.x * blockDim.x + threadIdx.x; i < n4; i += stride) {
        float4 a = img4[i];
        float4 t = tgt[i];
        img4[i] = zero4;  // reset for next replay
        float dx = a.x - t.x;
        float dy = a.y - t.y;
        float dz = a.z - t.z;
        float dw = a.w - t.w;
        acc = fmaf(dx, dx, acc);
        acc = fmaf(dy, dy, acc);
        acc = fmaf(dz, dz, acc);
        acc = fmaf(dw, dw, acc);
    }

    // block reduce in double
    double dacc = (double)acc;
    __shared__ double sred[32];
    int lane = threadIdx.x & 31;
    int wid  = threadIdx.x >> 5;
    #pragma unroll
    for (int off = 16; off > 0; off >>= 1)
        dacc += __shfl_down_sync(0xFFFFFFFFu, dacc, off);
    if (lane == 0) sred[wid] = dacc;
    __syncthreads();
    if (wid == 0) {
        double v = (lane < (int)(blockDim.x >> 5)) ? sred[lane] : 0.0;
        #pragma unroll
        for (int off = 16; off > 0; off >>= 1)
            v += __shfl_down_sync(0xFFFFFFFFu, v, off);
        if (lane == 0) atomicAdd(&g_sum, v);
    }
}

__global__ void finalize_kernel(float* __restrict__ out) {
    out[0] = (float)(g_sum / (double)NPIX);
}

extern "C" void kernel_launch(void* const* d_in, const int* in_sizes, int n_in,
                              void* d_out, int out_size) {
    const float* pts = (const float*)d_in[0];       // [B, N, 3]
    const float4* tgt = (const float4*)d_in[1];     // [B, H, W]
    float* out = (float*)d_out;

    init_kernel<<<1, 1>>>();
    splat_kernel<<<(BB * NN + 255) / 256, 256>>>(pts);
    loss_kernel<<<1184, 256>>>(tgt);
    finalize_kernel<<<1, 1>>>(out);
}

// round 3
// speedup vs baseline: 1.5289x; 1.5289x over previous
#include <cuda_runtime.h>

#define BB 128
#define NN 16384
#define HH 512
#define WW 512
#define NPIX ((size_t)BB * HH * WW)        // 33,554,432 pixels
#define PHASE_FRAMES 32                    // 32MB image slice -> L2-resident atomics
#define NPHASE (BB / PHASE_FRAMES)         // 4 phases
#define PHASE_PIX ((size_t)PHASE_FRAMES * HH * WW)

// Scratch image. __device__ globals are zero-initialized at module load;
// each phase's loss kernel resets its slice to zero after reading, preserving
// the "zero at entry" invariant across graph replays.
__device__ float g_img[BB * HH * WW];
__device__ double g_sum;

__global__ void init_kernel() { g_sum = 0.0; }

__global__ void splat_kernel(const float* __restrict__ pts, int frame_base) {
    int idx = blockIdx.x * blockDim.x + threadIdx.x;
    if (idx >= PHASE_FRAMES * NN) return;

    int gidx = frame_base * NN + idx;      // global point index
    float x     = pts[gidx * 3 + 0];
    float y     = pts[gidx * 3 + 1];
    float inten = pts[gidx * 3 + 2];

    x = fminf(fmaxf(x, 0.0f), (float)(WW - 1));
    y = fminf(fmaxf(y, 0.0f), (float)(HH - 1));
    float x0f = floorf(x);
    float y0f = floorf(y);
    float fx = x - x0f;
    float fy = y - y0f;
    int x0 = (int)x0f;
    int y0 = (int)y0f;
    int x1 = min(x0 + 1, WW - 1);
    int y1 = min(y0 + 1, HH - 1);

    int b = frame_base + idx / NN;
    float* img = g_img + (size_t)b * HH * WW;

    float w00 = inten * (1.0f - fx) * (1.0f - fy);
    float w01 = inten * fx * (1.0f - fy);
    float w10 = inten * (1.0f - fx) * fy;
    float w11 = inten * fx * fy;

    atomicAdd(&img[y0 * WW + x0], w00);   // return unused -> REDG, L2-resident
    atomicAdd(&img[y0 * WW + x1], w01);
    atomicAdd(&img[y1 * WW + x0], w10);
    atomicAdd(&img[y1 * WW + x1], w11);
}

// Read img slice (hot in L2) + targets, accumulate squared diff, reset img slice.
__global__ void loss_kernel(const float4* __restrict__ tgt, int frame_base) {
    const size_t base4 = (size_t)frame_base * HH * WW / 4;
    float4* img4 = reinterpret_cast<float4*>(g_img) + base4;
    const float4* tgt4 = tgt + base4;
    const size_t n4 = PHASE_PIX / 4;
    size_t stride = (size_t)gridDim.x * blockDim.x;
    float acc = 0.0f;

    const float4 zero4 = make_float4(0.f, 0.f, 0.f, 0.f);
    for (size_t i = (size_t)blockIdx.x * blockDim.x + threadIdx.x; i < n4; i += stride) {
        float4 a = img4[i];
        float4 t = tgt4[i];
        img4[i] = zero4;  // reset for next replay
        float dx = a.x - t.x;
        float dy = a.y - t.y;
        float dz = a.z - t.z;
        float dw = a.w - t.w;
        acc = fmaf(dx, dx, acc);
        acc = fmaf(dy, dy, acc);
        acc = fmaf(dz, dz, acc);
        acc = fmaf(dw, dw, acc);
    }

    // block reduce in double
    double dacc = (double)acc;
    __shared__ double sred[32];
    int lane = threadIdx.x & 31;
    int wid  = threadIdx.x >> 5;
    #pragma unroll
    for (int off = 16; off > 0; off >>= 1)
        dacc += __shfl_down_sync(0xFFFFFFFFu, dacc, off);
    if (lane == 0) sred[wid] = dacc;
    __syncthreads();
    if (wid == 0) {
        double v = (lane < (int)(blockDim.x >> 5)) ? sred[lane] : 0.0;
        #pragma unroll
        for (int off = 16; off > 0; off >>= 1)
            v += __shfl_down_sync(0xFFFFFFFFu, v, off);
        if (lane == 0) atomicAdd(&g_sum, v);
    }
}

__global__ void finalize_kernel(float* __restrict__ out) {
    out[0] = (float)(g_sum / (double)NPIX);
}

extern "C" void kernel_launch(void* const* d_in, const int* in_sizes, int n_in,
                              void* d_out, int out_size) {
    const float* pts = (const float*)d_in[0];       // [B, N, 3]
    const float4* tgt = (const float4*)d_in[1];     // [B, H, W]
    float* out = (float*)d_out;

    init_kernel<<<1, 1>>>();
    for (int p = 0; p < NPHASE; p++) {
        int frame_base = p * PHASE_FRAMES;
        splat_kernel<<<(PHASE_FRAMES * NN + 255) / 256, 256>>>(pts, frame_base);
        loss_kernel<<<1184, 256>>>(tgt, frame_base);
    }
    finalize_kernel<<<1, 1>>>(out);
}

// round 8
// speedup vs baseline: 2.2737x; 1.4872x over previous
#include <cuda_runtime.h>

#define BB 128
#define NN 16384
#define HH 512
#define WW 512
#define NPIX ((size_t)BB * HH * WW)        // 33,554,432 pixels
#define PHASE_FRAMES 32                    // 32MB image slice -> L2-resident atomics
#define NPHASE (BB / PHASE_FRAMES)         // 4 phases
#define PHASE_PIX ((unsigned)PHASE_FRAMES * HH * WW)      // 8,388,608
#define PHASE_F4  (PHASE_PIX / 4)                          // 2,097,152 float4

#define SPLAT_BLOCKS 2048                  // 2048*256 = 524288 = points/phase
#define LOSS_BLOCKS  2048                  // 2048*256*4 = 2097152 = float4/phase
#define LOSS_ITERS   4

// Scratch image. __device__ globals are zero-initialized at module load;
// the loss pass resets its slice to zero after reading, preserving the
// "zero at entry" invariant across graph replays.
__device__ float g_img[BB * HH * WW];
__device__ double g_sum;

__global__ void init_kernel() { g_sum = 0.0; }

__device__ __forceinline__ void splat_body(const float* __restrict__ pts,
                                           int frame_base, int blk) {
    int idx = blk * blockDim.x + threadIdx.x;   // 0 .. 524287
    int gidx = frame_base * NN + idx;           // global point index

    float x     = __ldcs(&pts[gidx * 3 + 0]);
    float y     = __ldcs(&pts[gidx * 3 + 1]);
    float inten = __ldcs(&pts[gidx * 3 + 2]);

    x = fminf(fmaxf(x, 0.0f), (float)(WW - 1));
    y = fminf(fmaxf(y, 0.0f), (float)(HH - 1));
    float x0f = floorf(x);
    float y0f = floorf(y);
    float fx = x - x0f;
    float fy = y - y0f;
    int x0 = (int)x0f;
    int y0 = (int)y0f;
    int x1 = min(x0 + 1, WW - 1);
    int y1 = min(y0 + 1, HH - 1);

    int b = frame_base + idx / NN;
    float* img = g_img + (size_t)b * HH * WW;

    float w00 = inten * (1.0f - fx) * (1.0f - fy);
    float w01 = inten * fx * (1.0f - fy);
    float w10 = inten * (1.0f - fx) * fy;
    float w11 = inten * fx * fy;

    atomicAdd(&img[y0 * WW + x0], w00);   // REDG, L2-resident slice
    atomicAdd(&img[y0 * WW + x1], w01);
    atomicAdd(&img[y1 * WW + x0], w10);
    atomicAdd(&img[y1 * WW + x1], w11);
}

__device__ __forceinline__ void loss_body(const float4* __restrict__ tgt,
                                          int frame_base, int blk) {
    const unsigned base4 = (unsigned)frame_base * (HH * WW / 4);
    float4* img4 = reinterpret_cast<float4*>(g_img) + base4;
    const float4* tgt4 = tgt + base4;

    unsigned tid = (unsigned)blk * blockDim.x + threadIdx.x;   // 0 .. 524287
    const unsigned stride = LOSS_BLOCKS * 256u;

    float acc = 0.0f;
    const float4 zero4 = make_float4(0.f, 0.f, 0.f, 0.f);
    #pragma unroll
    for (int it = 0; it < LOSS_ITERS; it++) {
        unsigned i = tid + (unsigned)it * stride;
        float4 a = __ldcg(&img4[i]);   // L2-hot from splat
        float4 t = __ldcs(&tgt4[i]);   // pure stream, evict-first
        __stcs(&img4[i], zero4);       // reset for next replay, evict-first
        float dx = a.x - t.x;
        float dy = a.y - t.y;
        float dz = a.z - t.z;
        float dw = a.w - t.w;
        acc = fmaf(dx, dx, acc);
        acc = fmaf(dy, dy, acc);
        acc = fmaf(dz, dz, acc);
        acc = fmaf(dw, dw, acc);
    }

    // block reduce in double
    double dacc = (double)acc;
    __shared__ double sred[8];
    int lane = threadIdx.x & 31;
    int wid  = threadIdx.x >> 5;
    #pragma unroll
    for (int off = 16; off > 0; off >>= 1)
        dacc += __shfl_down_sync(0xFFFFFFFFu, dacc, off);
    if (lane == 0) sred[wid] = dacc;
    __syncthreads();
    if (wid == 0) {
        double v = (lane < 8) ? sred[lane] : 0.0;
        #pragma unroll
        for (int off = 4; off > 0; off >>= 1)
            v += __shfl_down_sync(0xFFFFFFFFu, v, off);
        if (lane == 0) atomicAdd(&g_sum, v);
    }
}

// Pipelined kernel: blocks [0, SPLAT_BLOCKS) splat phase `splat_phase`,
// blocks [SPLAT_BLOCKS, +LOSS_BLOCKS) run loss on phase `loss_phase`.
// A phase of -1 disables that half.
__global__ void __launch_bounds__(256) pipe_kernel(const float* __restrict__ pts,
                                                   const float4* __restrict__ tgt,
                                                   int splat_phase, int loss_phase) {
    int blk = blockIdx.x;
    if (blk < SPLAT_BLOCKS) {
        if (splat_phase >= 0)
            splat_body(pts, splat_phase * PHASE_FRAMES, blk);
    } else {
        if (loss_phase >= 0)
            loss_body(tgt, loss_phase * PHASE_FRAMES, blk - SPLAT_BLOCKS);
    }
}

__global__ void finalize_kernel(float* __restrict__ out) {
    out[0] = (float)(g_sum / (double)NPIX);
}

extern "C" void kernel_launch(void* const* d_in, const int* in_sizes, int n_in,
                              void* d_out, int out_size) {
    const float* pts = (const float*)d_in[0];       // [B, N, 3]
    const float4* tgt = (const float4*)d_in[1];     // [B, H, W]
    float* out = (float*)d_out;

    const int total_blocks = SPLAT_BLOCKS + LOSS_BLOCKS;

    init_kernel<<<1, 1>>>();
    // Pipeline: splat(p) must complete before loss(p); splat(p+1) overlaps loss(p).
    pipe_kernel<<<total_blocks, 256>>>(pts, tgt, 0, -1);
    pipe_kernel<<<total_blocks, 256>>>(pts, tgt, 1, 0);
    pipe_kernel<<<total_blocks, 256>>>(pts, tgt, 2, 1);
    pipe_kernel<<<total_blocks, 256>>>(pts, tgt, 3, 2);
    pipe_kernel<<<total_blocks, 256>>>(pts, tgt, -1, 3);
    finalize_kernel<<<1, 1>>>(out);
}

// round 9
// speedup vs baseline: 3.2740x; 1.4399x over previous
#include <cuda_runtime.h>

#define BB 128
#define NN 16384
#define HH 512
#define WW 512
#define NPIX ((size_t)BB * HH * WW)        // 33,554,432 pixels
#define PHASE_FRAMES 32                    // 32MB image slice -> L2-resident atomics
#define NPHASE (BB / PHASE_FRAMES)         // 4 phases
#define PHASE_PTS (PHASE_FRAMES * NN)      // 524,288 points / phase
#define PHASE_F4  ((unsigned)PHASE_FRAMES * HH * WW / 4)   // 2,097,152 float4

#define SPLAT_BLOCKS 512                   // 512*256*4 pts = 524288 = points/phase
#define LOSS_BLOCKS  2048                  // 2048*256*4 = 2097152 = float4/phase
#define LOSS_ITERS   4
#define TOTAL_BLOCKS (SPLAT_BLOCKS + LOSS_BLOCKS)   // 2560; interleave 1:4

// Scratch image. __device__ globals are zero-initialized at module load;
// the loss pass resets its slice to zero after reading, and finalize resets
// g_sum after reading, preserving all invariants across graph replays.
__device__ float g_img[BB * HH * WW];
__device__ double g_sum;

// Splat 4 points per thread using 3 coalesced float4 loads.
__device__ __forceinline__ void splat_body(const float* __restrict__ pts,
                                           int frame_base, int sblk) {
    int t = threadIdx.x;
    int p0 = sblk * 1024 + 4 * t;              // point index within phase
    int g0 = frame_base * NN + p0;             // global point index
    const float4* p4 = reinterpret_cast<const float4*>(pts);
    size_t idx4 = ((size_t)g0 * 3) >> 2;       // g0*3 floats, /4 -> float4 idx

    float4 A = __ldcs(&p4[idx4 + 0]);
    float4 B = __ldcs(&p4[idx4 + 1]);
    float4 C = __ldcs(&p4[idx4 + 2]);

    float xs[4] = {A.x, A.w, B.z, C.y};
    float ys[4] = {A.y, B.x, B.w, C.z};
    float is[4] = {A.z, B.y, C.x, C.w};

    // 4 consecutive points share a frame (p0 aligned to 4, 4 | NN)
    int b = frame_base + p0 / NN;
    float* img = g_img + (size_t)b * HH * WW;

    #pragma unroll
    for (int k = 0; k < 4; k++) {
        float x = fminf(fmaxf(xs[k], 0.0f), (float)(WW - 1));
        float y = fminf(fmaxf(ys[k], 0.0f), (float)(HH - 1));
        float x0f = floorf(x);
        float y0f = floorf(y);
        float fx = x - x0f;
        float fy = y - y0f;
        int x0 = (int)x0f;
        int y0 = (int)y0f;
        int x1 = min(x0 + 1, WW - 1);
        int y1 = min(y0 + 1, HH - 1);
        float inten = is[k];
        float w00 = inten * (1.0f - fx) * (1.0f - fy);
        float w01 = inten * fx * (1.0f - fy);
        float w10 = inten * (1.0f - fx) * fy;
        float w11 = inten * fx * fy;
        atomicAdd(&img[y0 * WW + x0], w00);   // REDG, L2-resident slice
        atomicAdd(&img[y0 * WW + x1], w01);
        atomicAdd(&img[y1 * WW + x0], w10);
        atomicAdd(&img[y1 * WW + x1], w11);
    }
}

__device__ __forceinline__ void loss_body(const float4* __restrict__ tgt,
                                          int frame_base, int lblk) {
    const unsigned base4 = (unsigned)frame_base * (HH * WW / 4);
    float4* img4 = reinterpret_cast<float4*>(g_img) + base4;
    const float4* tgt4 = tgt + base4;

    unsigned tid = (unsigned)lblk * 256u + threadIdx.x;   // 0 .. 524287
    const unsigned stride = LOSS_BLOCKS * 256u;

    // Batch all loads first: 8 LDG.128 in flight before any dependent work.
    float4 a[LOSS_ITERS], tv[LOSS_ITERS];
    #pragma unroll
    for (int it = 0; it < LOSS_ITERS; it++) {
        unsigned i = tid + (unsigned)it * stride;
        a[it]  = __ldcg(&img4[i]);   // L2-hot from splat
        tv[it] = __ldcs(&tgt4[i]);   // pure stream, evict-first
    }
    const float4 zero4 = make_float4(0.f, 0.f, 0.f, 0.f);
    #pragma unroll
    for (int it = 0; it < LOSS_ITERS; it++) {
        unsigned i = tid + (unsigned)it * stride;
        __stcs(&img4[i], zero4);     // reset for next replay
    }
    float acc = 0.0f;
    #pragma unroll
    for (int it = 0; it < LOSS_ITERS; it++) {
        float dx = a[it].x - tv[it].x;
        float dy = a[it].y - tv[it].y;
        float dz = a[it].z - tv[it].z;
        float dw = a[it].w - tv[it].w;
        acc = fmaf(dx, dx, acc);
        acc = fmaf(dy, dy, acc);
        acc = fmaf(dz, dz, acc);
        acc = fmaf(dw, dw, acc);
    }

    // block reduce in double
    double dacc = (double)acc;
    __shared__ double sred[8];
    int lane = threadIdx.x & 31;
    int wid  = threadIdx.x >> 5;
    #pragma unroll
    for (int off = 16; off > 0; off >>= 1)
        dacc += __shfl_down_sync(0xFFFFFFFFu, dacc, off);
    if (lane == 0) sred[wid] = dacc;
    __syncthreads();
    if (wid == 0) {
        double v = (lane < 8) ? sred[lane] : 0.0;
        #pragma unroll
        for (int off = 4; off > 0; off >>= 1)
            v += __shfl_down_sync(0xFFFFFFFFu, v, off);
        if (lane == 0) atomicAdd(&g_sum, v);
    }
}

// Interleaved pipelined kernel: every 5th block splats phase `splat_phase`,
// the other 4/5 run loss on phase `loss_phase`. Interleaving by block index
// keeps both halves co-resident on every SM from the first wave, overlapping
// the LTS-bound atomic fill with the DRAM-bound loss stream.
__global__ void __launch_bounds__(256) pipe_kernel(const float* __restrict__ pts,
                                                   const float4* __restrict__ tgt,
                                                   int splat_phase, int loss_phase) {
    int blk = blockIdx.x;
    int s = blk / 5;
    int r = blk - 5 * s;
    if (r == 0) {
        if (splat_phase >= 0)
            splat_body(pts, splat_phase * PHASE_FRAMES, s);
    } else {
        if (loss_phase >= 0)
            loss_body(tgt, loss_phase * PHASE_FRAMES, s * 4 + (r - 1));
    }
}

__global__ void finalize_kernel(float* __restrict__ out) {
    out[0] = (float)(g_sum / (double)NPIX);
    g_sum = 0.0;   // reset for next replay (module load provides the first zero)
}

extern "C" void kernel_launch(void* const* d_in, const int* in_sizes, int n_in,
                              void* d_out, int out_size) {
    const float* pts = (const float*)d_in[0];       // [B, N, 3]
    const float4* tgt = (const float4*)d_in[1];     // [B, H, W]
    float* out = (float*)d_out;

    // Pipeline: splat(p) completes before loss(p); splat(p+1) overlaps loss(p).
    pipe_kernel<<<TOTAL_BLOCKS, 256>>>(pts, tgt, 0, -1);
    pipe_kernel<<<TOTAL_BLOCKS, 256>>>(pts, tgt, 1, 0);
    pipe_kernel<<<TOTAL_BLOCKS, 256>>>(pts, tgt, 2, 1);
    pipe_kernel<<<TOTAL_BLOCKS, 256>>>(pts, tgt, 3, 2);
    pipe_kernel<<<TOTAL_BLOCKS, 256>>>(pts, tgt, -1, 3);
    finalize_kernel<<<1, 1>>>(out);
}

// round 10
// speedup vs baseline: 3.3158x; 1.0128x over previous
#include <cuda_runtime.h>

#define BB 128
#define NN 16384
#define HH 512
#define WW 512
#define NPIX ((size_t)BB * HH * WW)        // 33,554,432 pixels
#define PHASE_FRAMES 16                    // 16MB image slice: whole pipeline stays in L2
#define NPHASE (BB / PHASE_FRAMES)         // 8 phases
#define PHASE_PTS (PHASE_FRAMES * NN)      // 262,144 points / phase
#define PHASE_F4  ((unsigned)PHASE_FRAMES * HH * WW / 4)   // 1,048,576 float4

#define SPLAT_BLOCKS 256                   // 256*256*4 pts = 262144 = points/phase
#define LOSS_BLOCKS  1024                  // 1024*256*4 = 1048576 = float4/phase
#define LOSS_ITERS   4
#define TOTAL_BLOCKS (SPLAT_BLOCKS + LOSS_BLOCKS)   // 1280 = ~1.08 waves; interleave 1:4

// Scratch image. __device__ globals are zero-initialized at module load;
// the loss pass resets its slice to zero after reading, and finalize resets
// g_sum after reading, preserving all invariants across graph replays.
__device__ float g_img[BB * HH * WW];
__device__ double g_sum;

// Splat 4 points per thread using 3 coalesced float4 loads.
__device__ __forceinline__ void splat_body(const float* __restrict__ pts,
                                           int frame_base, int sblk) {
    int t = threadIdx.x;
    int p0 = sblk * 1024 + 4 * t;              // point index within phase
    int g0 = frame_base * NN + p0;             // global point index
    const float4* p4 = reinterpret_cast<const float4*>(pts);
    size_t idx4 = ((size_t)g0 * 3) >> 2;       // g0*3 floats, /4 -> float4 idx

    float4 A = __ldcs(&p4[idx4 + 0]);
    float4 B = __ldcs(&p4[idx4 + 1]);
    float4 C = __ldcs(&p4[idx4 + 2]);

    float xs[4] = {A.x, A.w, B.z, C.y};
    float ys[4] = {A.y, B.x, B.w, C.z};
    float is[4] = {A.z, B.y, C.x, C.w};

    // 4 consecutive points share a frame (p0 aligned to 4, 4 | NN)
    int b = frame_base + p0 / NN;
    float* img = g_img + (size_t)b * HH * WW;

    #pragma unroll
    for (int k = 0; k < 4; k++) {
        float x = fminf(fmaxf(xs[k], 0.0f), (float)(WW - 1));
        float y = fminf(fmaxf(ys[k], 0.0f), (float)(HH - 1));
        float x0f = floorf(x);
        float y0f = floorf(y);
        float fx = x - x0f;
        float fy = y - y0f;
        int x0 = (int)x0f;
        int y0 = (int)y0f;
        int x1 = min(x0 + 1, WW - 1);
        int y1 = min(y0 + 1, HH - 1);
        float inten = is[k];
        float w00 = inten * (1.0f - fx) * (1.0f - fy);
        float w01 = inten * fx * (1.0f - fy);
        float w10 = inten * (1.0f - fx) * fy;
        float w11 = inten * fx * fy;
        atomicAdd(&img[y0 * WW + x0], w00);   // REDG, L2-resident slice
        atomicAdd(&img[y0 * WW + x1], w01);
        atomicAdd(&img[y1 * WW + x0], w10);
        atomicAdd(&img[y1 * WW + x1], w11);
    }
}

__device__ __forceinline__ void loss_body(const float4* __restrict__ tgt,
                                          int frame_base, int lblk) {
    const unsigned base4 = (unsigned)frame_base * (HH * WW / 4);
    float4* img4 = reinterpret_cast<float4*>(g_img) + base4;
    const float4* tgt4 = tgt + base4;

    unsigned tid = (unsigned)lblk * 256u + threadIdx.x;   // 0 .. 262143
    const unsigned stride = LOSS_BLOCKS * 256u;           // 262144

    // Batch all loads first: 8 LDG.128 in flight before any dependent work.
    float4 a[LOSS_ITERS], tv[LOSS_ITERS];
    #pragma unroll
    for (int it = 0; it < LOSS_ITERS; it++) {
        unsigned i = tid + (unsigned)it * stride;
        a[it]  = __ldcg(&img4[i]);   // L2-hot from splat
        tv[it] = __ldcs(&tgt4[i]);   // pure stream, evict-first
    }
    const float4 zero4 = make_float4(0.f, 0.f, 0.f, 0.f);
    #pragma unroll
    for (int it = 0; it < LOSS_ITERS; it++) {
        unsigned i = tid + (unsigned)it * stride;
        __stcg(&img4[i], zero4);     // reset for next replay; stays L2-resident
    }
    float acc = 0.0f;
    #pragma unroll
    for (int it = 0; it < LOSS_ITERS; it++) {
        float dx = a[it].x - tv[it].x;
        float dy = a[it].y - tv[it].y;
        float dz = a[it].z - tv[it].z;
        float dw = a[it].w - tv[it].w;
        acc = fmaf(dx, dx, acc);
        acc = fmaf(dy, dy, acc);
        acc = fmaf(dz, dz, acc);
        acc = fmaf(dw, dw, acc);
    }

    // block reduce in double
    double dacc = (double)acc;
    __shared__ double sred[8];
    int lane = threadIdx.x & 31;
    int wid  = threadIdx.x >> 5;
    #pragma unroll
    for (int off = 16; off > 0; off >>= 1)
        dacc += __shfl_down_sync(0xFFFFFFFFu, dacc, off);
    if (lane == 0) sred[wid] = dacc;
    __syncthreads();
    if (wid == 0) {
        double v = (lane < 8) ? sred[lane] : 0.0;
        #pragma unroll
        for (int off = 4; off > 0; off >>= 1)
            v += __shfl_down_sync(0xFFFFFFFFu, v, off);
        if (lane == 0) atomicAdd(&g_sum, v);
    }
}

// Interleaved pipelined kernel: every 5th block splats phase `splat_phase`,
// the other 4/5 run loss on phase `loss_phase`. Interleaving keeps both
// halves co-resident on every SM from the first wave, overlapping the
// LTS-bound atomic fill with the (mostly L2-resident) loss stream.
__global__ void __launch_bounds__(256) pipe_kernel(const float* __restrict__ pts,
                                                   const float4* __restrict__ tgt,
                                                   int splat_phase, int loss_phase) {
    int blk = blockIdx.x;
    int s = blk / 5;
    int r = blk - 5 * s;
    if (r == 0) {
        if (splat_phase >= 0)
            splat_body(pts, splat_phase * PHASE_FRAMES, s);
    } else {
        if (loss_phase >= 0)
            loss_body(tgt, loss_phase * PHASE_FRAMES, s * 4 + (r - 1));
    }
}

__global__ void finalize_kernel(float* __restrict__ out) {
    out[0] = (float)(g_sum / (double)NPIX);
    g_sum = 0.0;   // reset for next replay (module load provides the first zero)
}

extern "C" void kernel_launch(void* const* d_in, const int* in_sizes, int n_in,
                              void* d_out, int out_size) {
    const float* pts = (const float*)d_in[0];       // [B, N, 3]
    const float4* tgt = (const float4*)d_in[1];     // [B, H, W]
    float* out = (float*)d_out;

    // Pipeline: splat(p) completes before loss(p); splat(p+1) overlaps loss(p).
    pipe_kernel<<<TOTAL_BLOCKS, 256>>>(pts, tgt, 0, -1);
    #pragma unroll
    for (int p = 1; p < NPHASE; p++)
        pipe_kernel<<<TOTAL_BLOCKS, 256>>>(pts, tgt, p, p - 1);
    pipe_kernel<<<TOTAL_BLOCKS, 256>>>(pts, tgt, -1, NPHASE - 1);
    finalize_kernel<<<1, 1>>>(out);
}

// round 13
// speedup vs baseline: 4.4790x; 1.3508x over previous
#include <cuda_runtime.h>

#define BB 128
#define NN 16384
#define HH 512
#define WW 512
#define NPIX ((size_t)BB * HH * WW)        // 33,554,432 pixels
#define PHASE_FRAMES 16                    // 16MB image slice: pipeline lives in L2
#define NPHASE (BB / PHASE_FRAMES)         // 8 phases
#define PHASE_F4  ((unsigned)PHASE_FRAMES * HH * WW / 4)   // 1,048,576 float4

#define ZERO_BLOCKS  256                   // 256*256*16 f4 = 1048576 = slice
#define SPLAT_BLOCKS 256                   // 256*256*4 pts = 262144 = points/phase
#define LOSS_BLOCKS  1024                  // 1024*256*4 f4 = 1048576 = slice
#define LOSS_ITERS   4
#define TOTAL_BLOCKS (ZERO_BLOCKS + SPLAT_BLOCKS + LOSS_BLOCKS)   // 1536; 1:1:4 per 6

// Scratch image. Every call zeroes a slice before splatting it (stage 0 of the
// pipeline), so no cross-replay state is needed. Loss DISCARDS img lines from
// L2 after reading (no writeback) — img never touches DRAM.
__device__ __align__(128) float g_img[BB * HH * WW];
__device__ double g_sum;

// Zero one slice with full-line stores (no-fetch write-allocate: no DRAM read).
__device__ __forceinline__ void zero_body(int frame_base, int zblk) {
    float4* img4 = reinterpret_cast<float4*>(g_img)
                 + (size_t)frame_base * (HH * WW / 4);
    unsigned tid = (unsigned)zblk * 256u + threadIdx.x;    // 0 .. 65535
    const unsigned stride = ZERO_BLOCKS * 256u;            // 65536
    const float4 zero4 = make_float4(0.f, 0.f, 0.f, 0.f);
    #pragma unroll
    for (int it = 0; it < 16; it++)
        __stcg(&img4[tid + (unsigned)it * stride], zero4);
}

// Splat 4 points per thread using 3 coalesced float4 loads.
__device__ __forceinline__ void splat_body(const float* __restrict__ pts,
                                           int frame_base, int sblk) {
    int t = threadIdx.x;
    int p0 = sblk * 1024 + 4 * t;              // point index within phase
    int g0 = frame_base * NN + p0;             // global point index
    const float4* p4 = reinterpret_cast<const float4*>(pts);
    size_t idx4 = ((size_t)g0 * 3) >> 2;       // g0*3 floats, /4 -> float4 idx

    float4 A = __ldcs(&p4[idx4 + 0]);
    float4 B = __ldcs(&p4[idx4 + 1]);
    float4 C = __ldcs(&p4[idx4 + 2]);

    float xs[4] = {A.x, A.w, B.z, C.y};
    float ys[4] = {A.y, B.x, B.w, C.z};
    float is[4] = {A.z, B.y, C.x, C.w};

    // 4 consecutive points share a frame (p0 aligned to 4, 4 | NN)
    int b = frame_base + p0 / NN;
    float* img = g_img + (size_t)b * HH * WW;

    #pragma unroll
    for (int k = 0; k < 4; k++) {
        float x = fminf(fmaxf(xs[k], 0.0f), (float)(WW - 1));
        float y = fminf(fmaxf(ys[k], 0.0f), (float)(HH - 1));
        float x0f = floorf(x);
        float y0f = floorf(y);
        float fx = x - x0f;
        float fy = y - y0f;
        int x0 = (int)x0f;
        int y0 = (int)y0f;
        int x1 = min(x0 + 1, WW - 1);
        int y1 = min(y0 + 1, HH - 1);
        float inten = is[k];
        float w00 = inten * (1.0f - fx) * (1.0f - fy);
        float w01 = inten * fx * (1.0f - fy);
        float w10 = inten * (1.0f - fx) * fy;
        float w11 = inten * fx * fy;
        atomicAdd(&img[y0 * WW + x0], w00);   // REDG on L2-resident zeroed lines
        atomicAdd(&img[y0 * WW + x1], w01);
        atomicAdd(&img[y1 * WW + x0], w10);
        atomicAdd(&img[y1 * WW + x1], w11);
    }
}

__device__ __forceinline__ void loss_body(const float4* __restrict__ tgt,
                                          int frame_base, int lblk) {
    const size_t base4 = (size_t)frame_base * (HH * WW / 4);
    float4* img4 = reinterpret_cast<float4*>(g_img) + base4;
    const float4* tgt4 = tgt + base4;

    unsigned tid = (unsigned)lblk * 256u + threadIdx.x;   // 0 .. 262143
    const unsigned stride = LOSS_BLOCKS * 256u;           // 262144

    // Batch all loads first: 8 LDG.128 in flight before any dependent work.
    float4 a[LOSS_ITERS], tv[LOSS_ITERS];
    #pragma unroll
    for (int it = 0; it < LOSS_ITERS; it++) {
        unsigned i = tid + (unsigned)it * stride;
        a[it]  = __ldcg(&img4[i]);   // L2-hot from splat
        tv[it] = __ldcs(&tgt4[i]);   // pure stream, evict-first
    }
    float acc = 0.0f;
    #pragma unroll
    for (int it = 0; it < LOSS_ITERS; it++) {
        float dx = a[it].x - tv[it].x;
        float dy = a[it].y - tv[it].y;
        float dz = a[it].z - tv[it].z;
        float dw = a[it].w - tv[it].w;
        acc = fmaf(dx, dx, acc);
        acc = fmaf(dy, dy, acc);
        acc = fmaf(dz, dz, acc);
        acc = fmaf(dw, dw, acc);
    }

    // Drop img lines from L2 WITHOUT writeback. Data is consumed (acc depends
    // on it, so the warp's loads have drained). Lines become undefined; next
    // call re-zeroes the slice before splatting, so no one reads them again.
    // 8 consecutive threads (same warp) cover one 128B line; lane tid%8==0
    // issues the discard.
    if ((threadIdx.x & 7) == 0) {
        #pragma unroll
        for (int it = 0; it < LOSS_ITERS; it++) {
            unsigned i = tid + (unsigned)it * stride;
            asm volatile("discard.global.L2 [%0], 128;" :: "l"(&img4[i]) : "memory");
        }
    }

    // block reduce in double
    double dacc = (double)acc;
    __shared__ double sred[8];
    int lane = threadIdx.x & 31;
    int wid  = threadIdx.x >> 5;
    #pragma unroll
    for (int off = 16; off > 0; off >>= 1)
        dacc += __shfl_down_sync(0xFFFFFFFFu, dacc, off);
    if (lane == 0) sred[wid] = dacc;
    __syncthreads();
    if (wid == 0) {
        double v = (lane < 8) ? sred[lane] : 0.0;
        #pragma unroll
        for (int off = 4; off > 0; off >>= 1)
            v += __shfl_down_sync(0xFFFFFFFFu, v, off);
        if (lane == 0) atomicAdd(&g_sum, v);
    }
}

// 3-stage interleaved pipeline: per 6-block group, 1 zero / 1 splat / 4 loss.
// zero(zp) runs one launch before splat(zp), so splat atomics hit fresh
// dirty-zero lines in L2; loss(lp) reads the slice splatted last launch.
__global__ void __launch_bounds__(256) pipe_kernel(const float* __restrict__ pts,
                                                   const float4* __restrict__ tgt,
                                                   int zero_phase, int splat_phase,
                                                   int loss_phase) {
    int blk = blockIdx.x;
    int s = blk / 6;
    int r = blk - 6 * s;
    if (r == 0) {
        if (zero_phase >= 0)
            zero_body(zero_phase * PHASE_FRAMES, s);
    } else if (r == 1) {
        if (splat_phase >= 0)
            splat_body(pts, splat_phase * PHASE_FRAMES, s);
    } else {
        if (loss_phase >= 0)
            loss_body(tgt, loss_phase * PHASE_FRAMES, s * 4 + (r - 2));
    }
}

__global__ void finalize_kernel(float* __restrict__ out) {
    out[0] = (float)(g_sum / (double)NPIX);
    g_sum = 0.0;   // reset for next replay (module load provides the first zero)
}

extern "C" void kernel_launch(void* const* d_in, const int* in_sizes, int n_in,
                              void* d_out, int out_size) {
    const float* pts = (const float*)d_in[0];       // [B, N, 3]
    const float4* tgt = (const float4*)d_in[1];     // [B, H, W]
    float* out = (float*)d_out;

    // Launch k: zero(k), splat(k-1), loss(k-2); k = 0 .. NPHASE+1
    for (int k = 0; k < NPHASE + 2; k++) {
        int zp = (k < NPHASE)                ? k     : -1;
        int sp = (k >= 1 && k <= NPHASE)     ? k - 1 : -1;
        int lp = (k >= 2)                    ? k - 2 : -1;
        pipe_kernel<<<TOTAL_BLOCKS, 256>>>(pts, tgt, zp, sp, lp);
    }
    finalize_kernel<<<1, 1>>>(out);
}